// round 14
// baseline (speedup 1.0000x reference)
#include <cuda_runtime.h>
#include <cuda_bf16.h>
#include <cuda_fp16.h>
#include <math.h>

#define Lc 1024
#define Pc 2047

#define OUT_ELEMS  (8 * 1024 * 512)
#define ATTN_ELEMS (64LL * 1024 * 1024)

__device__ float g_q[(size_t)8192 * 512];
__device__ float g_inv[65536];
__device__ __half g_attn_raw[(size_t)ATTN_ELEMS];   // raw scores s, fp16
// fp16 single planes for attention operands
__device__ __half g_k[(size_t)64 * 1024 * 64];   // [bh][k][64]
__device__ __half g_v[(size_t)64 * 1024 * 64];   // [bh][k][64]
__device__ __half g_p[(size_t)8 * 2048 * 64];    // [h][p][64]; row 2047 stays zero
// fp16 single planes for qkv/pos GEMM operands
__device__ __half g_xf[(size_t)8192 * 512];
__device__ __half g_wqf[(size_t)1536 * 512];
__device__ __half g_wpf[(size_t)512 * 512];
__device__ __half g_psf[(size_t)2048 * 512];
// split-bf16 planes (hi/lo) for the out-proj GEMM
__device__ __nv_bfloat16 g_cth[(size_t)8192 * 512], g_ctl[(size_t)8192 * 512];
__device__ __nv_bfloat16 g_woh[(size_t)512 * 512],  g_wol[(size_t)512 * 512];

// ------------------------- helpers -------------------------------
__device__ __forceinline__ void mma_bf16(float* c, const unsigned* a,
                                         const unsigned* b) {
    asm volatile(
        "mma.sync.aligned.m16n8k16.row.col.f32.bf16.bf16.f32 "
        "{%0,%1,%2,%3}, {%4,%5,%6,%7}, {%8,%9}, {%0,%1,%2,%3};\n"
        : "+f"(c[0]), "+f"(c[1]), "+f"(c[2]), "+f"(c[3])
        : "r"(a[0]), "r"(a[1]), "r"(a[2]), "r"(a[3]), "r"(b[0]), "r"(b[1]));
}
__device__ __forceinline__ void mma_f16(float* c, const unsigned* a,
                                        const unsigned* b) {
    asm volatile(
        "mma.sync.aligned.m16n8k16.row.col.f32.f16.f16.f32 "
        "{%0,%1,%2,%3}, {%4,%5,%6,%7}, {%8,%9}, {%0,%1,%2,%3};\n"
        : "+f"(c[0]), "+f"(c[1]), "+f"(c[2]), "+f"(c[3])
        : "r"(a[0]), "r"(a[1]), "r"(a[2]), "r"(a[3]), "r"(b[0]), "r"(b[1]));
}
__device__ __forceinline__ void ldsm4(unsigned addr, unsigned& r0, unsigned& r1,
                                      unsigned& r2, unsigned& r3) {
    asm volatile("ldmatrix.sync.aligned.m8n8.x4.shared.b16 {%0,%1,%2,%3}, [%4];"
                 : "=r"(r0), "=r"(r1), "=r"(r2), "=r"(r3) : "r"(addr));
}
__device__ __forceinline__ void ldsm4t(unsigned addr, unsigned& r0, unsigned& r1,
                                       unsigned& r2, unsigned& r3) {
    asm volatile(
        "ldmatrix.sync.aligned.m8n8.x4.trans.shared.b16 {%0,%1,%2,%3}, [%4];"
        : "=r"(r0), "=r"(r1), "=r"(r2), "=r"(r3) : "r"(addr));
}
__device__ __forceinline__ unsigned s2u(const void* p) {
    return (unsigned)__cvta_generic_to_shared(p);
}
__device__ __forceinline__ void cpa16(unsigned dst, const void* src) {
    asm volatile("cp.async.cg.shared.global [%0], [%1], 16;\n" ::"r"(dst),
                 "l"(src));
}
__device__ __forceinline__ void pack_split(float x0, float x1, unsigned& h,
                                           unsigned& l) {
    __nv_bfloat162 hb = __floats2bfloat162_rn(x0, x1);
    float2 hf = __bfloat1622float2(hb);
    __nv_bfloat162 lb = __floats2bfloat162_rn(x0 - hf.x, x1 - hf.y);
    h = *(unsigned*)&hb; l = *(unsigned*)&lb;
}
__device__ __forceinline__ unsigned packh2(float x0, float x1) {
    __half2 t = __floats2half2_rn(x0, x1);
    return *(unsigned*)&t;
}

// ---------------------------------------------------------------------------
// One-shot conversion. fp16 single: x, wqkv, wpos, pos. split-bf16: wout.
// ---------------------------------------------------------------------------
__global__ __launch_bounds__(256) void cvt_all(
    const float* __restrict__ x, const float* __restrict__ wq,
    const float* __restrict__ wp, const float* __restrict__ wo,
    const float* __restrict__ pos) {
    int bid = blockIdx.x;
    if (bid < 10240 || bid >= 10752) {
        const float* src; __half* d; int base;
        if (bid < 8192)       { src = x;   d = g_xf;  base = bid; }
        else if (bid < 9728)  { src = wq;  d = g_wqf; base = bid - 8192; }
        else if (bid < 10240) { src = wp;  d = g_wpf; base = bid - 9728; }
        else                  { src = pos; d = g_psf; base = bid - 10752; }
        int i = base * 256 + threadIdx.x;
        float2 v = ((const float2*)src)[i];
        ((unsigned*)d)[i] = packh2(v.x, v.y);
    } else {
        int i = (bid - 10240) * 256 + threadIdx.x;
        float2 v = ((const float2*)wo)[i];
        unsigned h, l;
        pack_split(v.x, v.y, h, l);
        ((unsigned*)g_woh)[i] = h;
        ((unsigned*)g_wol)[i] = l;
    }
}

// ---------------------------------------------------------------------------
// Split-bf16 GEMM mainloop (K=512, 128x128 tile, cp.async dbuf) — out-proj.
// ---------------------------------------------------------------------------
#define GT 10240
#define GSTAGE (4 * GT)
#define GSM (2 * GSTAGE)

#define GEMM_MAIN(Ah, Al, Wh, Wl, m0, n0, acc)                                  \
    {                                                                           \
        const unsigned sb = s2u(smem);                                          \
        const int lrow = tid >> 2, lc = (tid & 3) << 3;                         \
        auto issue = [&](int k0, int bb) {                                      \
            unsigned base = sb + bb * GSTAGE;                                   \
            _Pragma("unroll") for (int t = 0; t < 2; t++) {                     \
                int row = lrow + t * 64;                                        \
                unsigned so = (unsigned)row * 80 + ((unsigned)lc << 1);         \
                size_t ao = (size_t)(m0 + row) * 512 + k0 + lc;                 \
                size_t wo_ = (size_t)(n0 + row) * 512 + k0 + lc;                \
                cpa16(base + so, Ah + ao);                                      \
                cpa16(base + GT + so, Al + ao);                                 \
                cpa16(base + 2 * GT + so, Wh + wo_);                            \
                cpa16(base + 3 * GT + so, Wl + wo_);                            \
            }                                                                   \
            asm volatile("cp.async.commit_group;\n" ::: "memory");              \
        };                                                                      \
        issue(0, 0);                                                            \
        for (int s = 0; s < 16; s++) {                                          \
            const int bb = s & 1;                                               \
            __syncthreads();                                                    \
            if (s < 15) {                                                       \
                issue((s + 1) << 5, bb ^ 1);                                    \
                asm volatile("cp.async.wait_group 1;\n" ::: "memory");          \
            } else {                                                            \
                asm volatile("cp.async.wait_group 0;\n" ::: "memory");          \
            }                                                                   \
            __syncthreads();                                                    \
            unsigned base = sb + bb * GSTAGE;                                   \
            _Pragma("unroll") for (int kc = 0; kc < 2; kc++) {                  \
                const int kk = kc << 4;                                         \
                unsigned ah[4][4], al[4][4], bh[4][2], bl[4][2];                \
                _Pragma("unroll") for (int mt = 0; mt < 4; mt++) {              \
                    unsigned off = ((aRow + mt * 16) * 40 + kk + aCol) * 2;     \
                    ldsm4(base + off, ah[mt][0], ah[mt][1], ah[mt][2],          \
                          ah[mt][3]);                                           \
                    ldsm4(base + GT + off, al[mt][0], al[mt][1], al[mt][2],     \
                          al[mt][3]);                                           \
                }                                                               \
                _Pragma("unroll") for (int np = 0; np < 2; np++) {              \
                    unsigned off = ((bRow + np * 16) * 40 + kk + bCol) * 2;     \
                    unsigned r0, r1, r2, r3;                                    \
                    ldsm4(base + 2 * GT + off, r0, r1, r2, r3);                 \
                    bh[np * 2][0] = r0; bh[np * 2][1] = r1;                     \
                    bh[np * 2 + 1][0] = r2; bh[np * 2 + 1][1] = r3;             \
                    ldsm4(base + 3 * GT + off, r0, r1, r2, r3);                 \
                    bl[np * 2][0] = r0; bl[np * 2][1] = r1;                     \
                    bl[np * 2 + 1][0] = r2; bl[np * 2 + 1][1] = r3;             \
                }                                                               \
                _Pragma("unroll") for (int mt = 0; mt < 4; mt++)                \
                    _Pragma("unroll") for (int nt = 0; nt < 4; nt++) {          \
                        mma_bf16(acc[mt][nt], ah[mt], bh[nt]);                  \
                        mma_bf16(acc[mt][nt], al[mt], bh[nt]);                  \
                        mma_bf16(acc[mt][nt], ah[mt], bl[nt]);                  \
                    }                                                           \
            }                                                                   \
        }                                                                       \
    }

// ---------------------------------------------------------------------------
// fp16-single GEMM mainloop — qkv/pos.
// ---------------------------------------------------------------------------
#define FT 10240
#define FSTAGE (2 * FT)
#define FSM (2 * FSTAGE)

#define GEMM_MAIN_F16(Af, Wf, m0, n0, acc)                                      \
    {                                                                           \
        const unsigned sb = s2u(smem);                                          \
        const int lrow = tid >> 2, lc = (tid & 3) << 3;                         \
        auto issue = [&](int k0, int bb) {                                      \
            unsigned base = sb + bb * FSTAGE;                                   \
            _Pragma("unroll") for (int t = 0; t < 2; t++) {                     \
                int row = lrow + t * 64;                                        \
                unsigned so = (unsigned)row * 80 + ((unsigned)lc << 1);         \
                cpa16(base + so, Af + (size_t)(m0 + row) * 512 + k0 + lc);      \
                cpa16(base + FT + so, Wf + (size_t)(n0 + row) * 512 + k0 + lc); \
            }                                                                   \
            asm volatile("cp.async.commit_group;\n" ::: "memory");              \
        };                                                                      \
        issue(0, 0);                                                            \
        for (int s = 0; s < 16; s++) {                                          \
            const int bb = s & 1;                                               \
            __syncthreads();                                                    \
            if (s < 15) {                                                       \
                issue((s + 1) << 5, bb ^ 1);                                    \
                asm volatile("cp.async.wait_group 1;\n" ::: "memory");          \
            } else {                                                            \
                asm volatile("cp.async.wait_group 0;\n" ::: "memory");          \
            }                                                                   \
            __syncthreads();                                                    \
            unsigned base = sb + bb * FSTAGE;                                   \
            _Pragma("unroll") for (int kc = 0; kc < 2; kc++) {                  \
                const int kk = kc << 4;                                         \
                unsigned af[4][4], bf[4][2];                                    \
                _Pragma("unroll") for (int mt = 0; mt < 4; mt++) {              \
                    unsigned off = ((aRow + mt * 16) * 40 + kk + aCol) * 2;     \
                    ldsm4(base + off, af[mt][0], af[mt][1], af[mt][2],          \
                          af[mt][3]);                                           \
                }                                                               \
                _Pragma("unroll") for (int np = 0; np < 2; np++) {              \
                    unsigned off = ((bRow + np * 16) * 40 + kk + bCol) * 2;     \
                    unsigned r0, r1, r2, r3;                                    \
                    ldsm4(base + FT + off, r0, r1, r2, r3);                     \
                    bf[np * 2][0] = r0; bf[np * 2][1] = r1;                     \
                    bf[np * 2 + 1][0] = r2; bf[np * 2 + 1][1] = r3;             \
                }                                                               \
                _Pragma("unroll") for (int mt = 0; mt < 4; mt++)                \
                    _Pragma("unroll") for (int nt = 0; nt < 4; nt++)            \
                        mma_f16(acc[mt][nt], af[mt], bf[nt]);                   \
            }                                                                   \
        }                                                                       \
    }

// ---------------------------------------------------------------------------
// Fused qkv-proj + pos-proj GEMM (fp16 single). 1-D grid, 832 blocks.
// ---------------------------------------------------------------------------
__global__ __launch_bounds__(256, 2) void gemm_qkv_pos() {
    extern __shared__ char smem[];
    const int tid = threadIdx.x, l = tid & 31, w = tid >> 5;
    const int wm = w >> 2, wn = w & 3;
    const int aRow = wm * 64 + (l & 15);
    const int aCol = (l & 16) >> 1;
    const int bRow = wn * 32 + (l & 7) + ((l & 16) >> 1);
    const int bCol = l & 8;

    const int bid = blockIdx.x;
    const __half *Af, *Wf;
    int m0, n0, mode;
    if (bid < 768) {
        Af = g_xf; Wf = g_wqf;
        m0 = (bid / 12) << 7; n0 = (bid % 12) << 7; mode = 1;
    } else {
        int t = bid - 768;
        Af = g_psf; Wf = g_wpf;
        m0 = (t >> 2) << 7; n0 = (t & 3) << 7; mode = 2;
    }

    float acc[4][4][4];
#pragma unroll
    for (int i = 0; i < 4; i++)
#pragma unroll
        for (int j = 0; j < 4; j++)
#pragma unroll
            for (int e = 0; e < 4; e++) acc[i][j][e] = 0.f;

    GEMM_MAIN_F16(Af, Wf, m0, n0, acc);

    const int er = m0 + wm * 64 + (l >> 2);
    const int ec = n0 + wn * 32 + ((l & 3) << 1);
#pragma unroll
    for (int mt = 0; mt < 4; mt++) {
#pragma unroll
        for (int nt = 0; nt < 4; nt++) {
            int col = ec + nt * 8;
#pragma unroll
            for (int half = 0; half < 2; half++) {
                int r = er + mt * 16 + half * 8;
                float a0 = acc[mt][nt][half * 2];
                float a1 = acc[mt][nt][half * 2 + 1];
                if (mode == 1) {
                    int hh_ = col / 192;
                    int rem = col - hh_ * 192;
                    int part = rem >> 6, d = rem & 63;
                    if (part == 0) {
                        *(float2*)&g_q[(size_t)r * 512 + hh_ * 64 + d] =
                            make_float2(a0, a1);
                    } else {
                        int b = r >> 10, ll2 = r & 1023;
                        size_t idx =
                            (((size_t)(b * 8 + hh_)) * 1024 + ll2) * 64 + d;
                        __half2 hv = __floats2half2_rn(a0, a1);
                        if (part == 1) *(__half2*)&g_k[idx] = hv;
                        else           *(__half2*)&g_v[idx] = hv;
                    }
                } else {
                    int hh_ = col >> 6, d = col & 63;
                    size_t idx = (((size_t)hh_) * 2048 + r) * 64 + d;
                    *(__half2*)&g_p[idx] = __floats2half2_rn(a0, a1);
                }
            }
        }
    }
}

// ---------------------------------------------------------------------------
// Standalone out-proj GEMM (split bf16): out = ctx @ wout^T + bias.
// ---------------------------------------------------------------------------
__global__ __launch_bounds__(256, 2) void gemm_out(
    const float* __restrict__ bias, float* __restrict__ C_ext) {
    extern __shared__ char smem[];
    const int tid = threadIdx.x, l = tid & 31, w = tid >> 5;
    const int wm = w >> 2, wn = w & 3;
    const int aRow = wm * 64 + (l & 15);
    const int aCol = (l & 16) >> 1;
    const int bRow = wn * 32 + (l & 7) + ((l & 16) >> 1);
    const int bCol = l & 8;
    const int m0 = blockIdx.y << 7, n0 = blockIdx.x << 7;

    float acc[4][4][4];
#pragma unroll
    for (int i = 0; i < 4; i++)
#pragma unroll
        for (int j = 0; j < 4; j++)
#pragma unroll
            for (int e = 0; e < 4; e++) acc[i][j][e] = 0.f;

    GEMM_MAIN(g_cth, g_ctl, g_woh, g_wol, m0, n0, acc);

    const int er = m0 + wm * 64 + (l >> 2);
    const int ec = n0 + wn * 32 + ((l & 3) << 1);
#pragma unroll
    for (int mt = 0; mt < 4; mt++) {
#pragma unroll
        for (int nt = 0; nt < 4; nt++) {
            int col = ec + nt * 8;
            float2 bb2 = *(const float2*)&bias[col];
#pragma unroll
            for (int half = 0; half < 2; half++) {
                int r = er + mt * 16 + half * 8;
                *(float2*)&C_ext[(size_t)r * 512 + col] =
                    make_float2(acc[mt][nt][half * 2] + bb2.x,
                                acc[mt][nt][half * 2 + 1] + bb2.y);
            }
        }
    }
}

// ---------------------------------------------------------------------------
// Fused attention. Grid (8, 64), 256 thr, 2 CTA/SM.
// Stores RAW fp16 scores to g_attn_raw; row inverses to g_inv. No rescale.
// ---------------------------------------------------------------------------
#define AP0 0
#define AK0 55296
#define AV0 73728
#define ASCRH 92160
#define SM_BYTES_A 113664

__global__ __launch_bounds__(256, 2) void attn_kernel(
    const float* __restrict__ ubias, const float* __restrict__ vbias) {
    extern __shared__ char smem[];

    const int tid = threadIdx.x, l = tid & 31, w = tid >> 5;
    const int bh = blockIdx.y, b = bh >> 3, h = bh & 7;
    const int q0 = blockIdx.x << 7;
    const int qs = w << 4;
    const float scale = 0.04419417382415922f;  // 1/sqrt(512)

    const unsigned pB0 = s2u(smem + AP0);
    const unsigned kB0 = s2u(smem + AK0);
    const unsigned vB0 = s2u(smem + AV0);
    __half* scrh = (__half*)(smem + ASCRH) + w * 16 * 84;

    // ---- QU/QV staging (overlaps P buffers; consumed before first tile) ----
    {
        __half* QU = (__half*)(smem + 0);
        __half* QV = (__half*)(smem + 18432);
        for (int idx = tid; idx < 4096; idx += 256) {
            int qi = idx >> 5, d2 = (idx & 31) << 1;
            float2 qv = *(const float2*)&g_q[((size_t)(b * Lc + q0 + qi)) * 512 +
                                             h * 64 + d2];
            *(unsigned*)&QU[qi * 72 + d2] =
                packh2((qv.x + ubias[h * 64 + d2]) * scale,
                       (qv.y + ubias[h * 64 + d2 + 1]) * scale);
            *(unsigned*)&QV[qi * 72 + d2] =
                packh2((qv.x + vbias[h * 64 + d2]) * scale,
                       (qv.y + vbias[h * 64 + d2 + 1]) * scale);
        }
    }
    __syncthreads();

    unsigned au[4][4], av[4][4];
    {
        unsigned baseU = s2u(smem + 0), baseV = s2u(smem + 18432);
        int row = qs + (l & 15), colp = (l & 16) >> 1;
#pragma unroll
        for (int kc = 0; kc < 4; kc++) {
            unsigned off = (row * 72 + kc * 16 + colp) * 2;
            ldsm4(baseU + off, au[kc][0], au[kc][1], au[kc][2], au[kc][3]);
            ldsm4(baseV + off, av[kc][0], av[kc][1], av[kc][2], av[kc][3]);
        }
    }
    __syncthreads();

    auto issue_tile = [&](int kt0, int bb) {
        size_t gb = (((size_t)bh) * 1024 + kt0) * 64;
        const uint4* GK = (const uint4*)(g_k + gb);
        const uint4* GV = (const uint4*)(g_v + gb);
        int pbase = kt0 - q0 + 896;
        const uint4* GP = (const uint4*)(g_p + (((size_t)h) * 2048 + pbase) * 64);
        unsigned kb = kB0 + bb * 9216;
        unsigned vb = vB0 + bb * 9216;
        unsigned pb = pB0 + bb * 27648;
#pragma unroll
        for (int t = 0; t < 2; t++) {
            int i = tid + t * 256;
            unsigned so = (unsigned)((i >> 3) * 9 + (i & 7)) * 16;
            cpa16(kb + so, GK + i);
            cpa16(vb + so, GV + i);
        }
#pragma unroll
        for (int t = 0; t < 6; t++) {
            int i = tid + t * 256;
            unsigned so = (unsigned)((i >> 3) * 9 + (i & 7)) * 16;
            cpa16(pb + so, GP + i);
        }
        asm volatile("cp.async.commit_group;\n" ::: "memory");
    };

    issue_tile(0, 0);

    float ct[8][4];
#pragma unroll
    for (int nt = 0; nt < 8; nt++)
#pragma unroll
        for (int e = 0; e < 4; e++) ct[nt][e] = 0.f;
    float rs_lo = 0.f, rs_hi = 0.f;

    const int nlane = (l & 7) + ((l & 16) >> 1);
    const int klane = l & 8;
    const int tkl = (l & 7) + (l & 8);
    const int tnl = (l & 16) >> 1;
    const int r0w = 112 - qs;

    for (int kt = 0; kt < 16; kt++) {
        const int bb = kt & 1;
        const int kt0 = kt << 6;
        __syncthreads();
        if (kt < 15) {
            issue_tile(kt0 + 64, bb ^ 1);
            asm volatile("cp.async.wait_group 1;\n" ::: "memory");
        } else {
            asm volatile("cp.async.wait_group 0;\n" ::: "memory");
        }
        __syncthreads();

        const unsigned kB = kB0 + bb * 9216;
        const unsigned vB = vB0 + bb * 9216;
        const unsigned pB = pB0 + bb * 27648;

        float bd[10][4];
#pragma unroll
        for (int nt = 0; nt < 10; nt++)
#pragma unroll
            for (int e = 0; e < 4; e++) bd[nt][e] = 0.f;
#pragma unroll
        for (int np = 0; np < 5; np++) {
            int nb = r0w + np * 16 + nlane;
#pragma unroll
            for (int kc = 0; kc < 4; kc++) {
                unsigned r0, r1, r2, r3;
                ldsm4(pB + (nb * 72 + kc * 16 + klane) * 2, r0, r1, r2, r3);
                unsigned b0[2] = {r0, r1}, b1[2] = {r2, r3};
                mma_f16(bd[np * 2], av[kc], b0);
                mma_f16(bd[np * 2 + 1], av[kc], b1);
            }
        }
        {
            int r = l >> 2, col = ((l & 3) << 1);
#pragma unroll
            for (int nt = 0; nt < 10; nt++) {
                *(__half2*)&scrh[r * 84 + nt * 8 + col] =
                    __floats2half2_rn(bd[nt][0], bd[nt][1]);
                *(__half2*)&scrh[(r + 8) * 84 + nt * 8 + col] =
                    __floats2half2_rn(bd[nt][2], bd[nt][3]);
            }
        }
        __syncwarp();

        float sc[8][4];
#pragma unroll
        for (int nt = 0; nt < 8; nt++)
#pragma unroll
            for (int e = 0; e < 4; e++) sc[nt][e] = 0.f;
#pragma unroll
        for (int np = 0; np < 4; np++) {
            int nb = np * 16 + nlane;
#pragma unroll
            for (int kc = 0; kc < 4; kc++) {
                unsigned r0, r1, r2, r3;
                ldsm4(kB + (nb * 72 + kc * 16 + klane) * 2, r0, r1, r2, r3);
                unsigned b0[2] = {r0, r1}, b1[2] = {r2, r3};
                mma_f16(sc[np * 2], au[kc], b0);
                mma_f16(sc[np * 2 + 1], au[kc], b1);
            }
        }

        // ---- add banded bd; store RAW fp16 scores; exp; rowsum ----
        {
            int r = l >> 2;
#pragma unroll
            for (int nt = 0; nt < 8; nt++) {
                int kk = nt * 8 + ((l & 3) << 1);
                int j = kk - r + 15;
                sc[nt][0] += __half2float(scrh[r * 84 + j]);
                sc[nt][1] += __half2float(scrh[r * 84 + j + 1]);
                int j2 = kk - (r + 8) + 15;
                sc[nt][2] += __half2float(scrh[(r + 8) * 84 + j2]);
                sc[nt][3] += __half2float(scrh[(r + 8) * 84 + j2 + 1]);
            }
            size_t rbase =
                ((size_t)bh * Lc + (q0 + qs + r)) * Lc + kt0 + ((l & 3) << 1);
#pragma unroll
            for (int nt = 0; nt < 8; nt++) {
                *(__half2*)&g_attn_raw[rbase + nt * 8] =
                    __floats2half2_rn(sc[nt][0], sc[nt][1]);
                *(__half2*)&g_attn_raw[rbase + 8 * Lc + nt * 8] =
                    __floats2half2_rn(sc[nt][2], sc[nt][3]);
            }
#pragma unroll
            for (int nt = 0; nt < 8; nt++) {
#pragma unroll
                for (int e = 0; e < 4; e++) sc[nt][e] = __expf(sc[nt][e]);
                rs_lo += sc[nt][0] + sc[nt][1];
                rs_hi += sc[nt][2] + sc[nt][3];
            }
        }

        // ---- ctx += P @ V ----
#pragma unroll
        for (int kc = 0; kc < 4; kc++) {
            unsigned pa[4];
            pa[0] = packh2(sc[2 * kc][0], sc[2 * kc][1]);
            pa[1] = packh2(sc[2 * kc][2], sc[2 * kc][3]);
            pa[2] = packh2(sc[2 * kc + 1][0], sc[2 * kc + 1][1]);
            pa[3] = packh2(sc[2 * kc + 1][2], sc[2 * kc + 1][3]);
            int krow = kc * 16 + tkl;
#pragma unroll
            for (int np = 0; np < 4; np++) {
                unsigned r0, r1, r2, r3;
                ldsm4t(vB + (krow * 72 + np * 16 + tnl) * 2, r0, r1, r2, r3);
                unsigned b0[2] = {r0, r1}, b1[2] = {r2, r3};
                mma_f16(ct[np * 2], pa, b0);
                mma_f16(ct[np * 2 + 1], pa, b1);
            }
        }
    }

    // ---- rowsum reduce; write g_inv; store ctx planes ----
    rs_lo += __shfl_xor_sync(0xffffffffu, rs_lo, 1);
    rs_lo += __shfl_xor_sync(0xffffffffu, rs_lo, 2);
    rs_hi += __shfl_xor_sync(0xffffffffu, rs_hi, 1);
    rs_hi += __shfl_xor_sync(0xffffffffu, rs_hi, 2);
    float inv_lo = 1.f / rs_lo, inv_hi = 1.f / rs_hi;
    int r = l >> 2;
    if ((l & 3) == 0) {
        g_inv[bh * Lc + q0 + qs + r] = inv_lo;
        g_inv[bh * Lc + q0 + qs + r + 8] = inv_hi;
    }
    size_t cbase = ((size_t)(b * Lc + q0 + qs + r)) * 512 + h * 64 + ((l & 3) << 1);
#pragma unroll
    for (int nt = 0; nt < 8; nt++) {
        unsigned hh, lo;
        pack_split(ct[nt][0] * inv_lo, ct[nt][1] * inv_lo, hh, lo);
        *(unsigned*)&g_cth[cbase + nt * 8] = hh;
        *(unsigned*)&g_ctl[cbase + nt * 8] = lo;
        pack_split(ct[nt][2] * inv_hi, ct[nt][3] * inv_hi, hh, lo);
        *(unsigned*)&g_cth[cbase + 8 * 512 + nt * 8] = hh;
        *(unsigned*)&g_ctl[cbase + 8 * 512 + nt * 8] = lo;
    }
}

// ---------------------------------------------------------------------------
// Normalize: attn = exp(raw) * inv, fp16 raw -> fp32 output. Full occupancy.
// 4096 blocks x 256 thr; 8 uint4 (64 halves) per thread, grid-strided.
// ---------------------------------------------------------------------------
__global__ __launch_bounds__(256) void norm_out(float* __restrict__ attn) {
    const uint4* R = (const uint4*)g_attn_raw;
    float4* O = (float4*)attn;
    int t = blockIdx.x * 256 + threadIdx.x;
#pragma unroll
    for (int j = 0; j < 8; j++) {
        size_t i = (size_t)t + (size_t)j * 1048576;
        uint4 rv = R[i];
        float inv = g_inv[i >> 7];
        const __half2* hp = (const __half2*)&rv;
        float4 o0, o1;
        float2 p0 = __half22float2(hp[0]);
        float2 p1 = __half22float2(hp[1]);
        float2 p2 = __half22float2(hp[2]);
        float2 p3 = __half22float2(hp[3]);
        o0.x = __expf(p0.x) * inv; o0.y = __expf(p0.y) * inv;
        o0.z = __expf(p1.x) * inv; o0.w = __expf(p1.y) * inv;
        o1.x = __expf(p2.x) * inv; o1.y = __expf(p2.y) * inv;
        o1.z = __expf(p3.x) * inv; o1.w = __expf(p3.y) * inv;
        O[i * 2] = o0;
        O[i * 2 + 1] = o1;
    }
}

// ---------------------------------------------------------------------------
extern "C" void kernel_launch(void* const* d_in, const int* in_sizes, int n_in,
                              void* d_out, int out_size) {
    const float* x    = (const float*)d_in[0];
    const float* pos  = (const float*)d_in[1];
    const float* wqkv = (const float*)d_in[2];
    const float* wpos = (const float*)d_in[3];
    const float* wout = (const float*)d_in[4];
    const float* bout = (const float*)d_in[5];
    const float* ub   = (const float*)d_in[6];
    const float* vb   = (const float*)d_in[7];
    float* out = (float*)d_out;

    int attn_in_out = ((long long)out_size >= (long long)OUT_ELEMS + ATTN_ELEMS);
    float* attn_buf = out + OUT_ELEMS;

    cvt_all<<<12799, 256>>>(x, wqkv, wpos, wout, pos);

    cudaFuncSetAttribute(gemm_qkv_pos, cudaFuncAttributeMaxDynamicSharedMemorySize,
                         FSM);
    gemm_qkv_pos<<<832, 256, FSM>>>();

    cudaFuncSetAttribute(attn_kernel, cudaFuncAttributeMaxDynamicSharedMemorySize,
                         SM_BYTES_A);
    attn_kernel<<<dim3(8, 64), 256, SM_BYTES_A>>>(ub, vb);

    if (attn_in_out) norm_out<<<4096, 256>>>(attn_buf);

    cudaFuncSetAttribute(gemm_out, cudaFuncAttributeMaxDynamicSharedMemorySize,
                         GSM);
    gemm_out<<<dim3(4, 64), 256, GSM>>>(bout, out);
}

// round 15
// speedup vs baseline: 1.0546x; 1.0546x over previous
#include <cuda_runtime.h>
#include <cuda_bf16.h>
#include <cuda_fp16.h>
#include <math.h>

#define Lc 1024
#define Pc 2047

#define OUT_ELEMS  (8 * 1024 * 512)
#define ATTN_ELEMS (64LL * 1024 * 1024)

__device__ float g_q[(size_t)8192 * 512];
__device__ __half g_attn_raw[(size_t)ATTN_ELEMS];   // exp'd probs, fp16
// fp16 single planes for attention operands
__device__ __half g_k[(size_t)64 * 1024 * 64];   // [bh][k][64]
__device__ __half g_v[(size_t)64 * 1024 * 64];   // [bh][k][64]
__device__ __half g_p[(size_t)8 * 2048 * 64];    // [h][p][64]; row 2047 stays zero
// fp16 single planes for qkv/pos GEMM operands
__device__ __half g_xf[(size_t)8192 * 512];
__device__ __half g_wqf[(size_t)1536 * 512];
__device__ __half g_wpf[(size_t)512 * 512];
__device__ __half g_psf[(size_t)2048 * 512];
// split-bf16 planes (hi/lo) for the out-proj GEMM
__device__ __nv_bfloat16 g_cth[(size_t)8192 * 512], g_ctl[(size_t)8192 * 512];
__device__ __nv_bfloat16 g_woh[(size_t)512 * 512],  g_wol[(size_t)512 * 512];

// ------------------------- helpers -------------------------------
__device__ __forceinline__ void mma_bf16(float* c, const unsigned* a,
                                         const unsigned* b) {
    asm volatile(
        "mma.sync.aligned.m16n8k16.row.col.f32.bf16.bf16.f32 "
        "{%0,%1,%2,%3}, {%4,%5,%6,%7}, {%8,%9}, {%0,%1,%2,%3};\n"
        : "+f"(c[0]), "+f"(c[1]), "+f"(c[2]), "+f"(c[3])
        : "r"(a[0]), "r"(a[1]), "r"(a[2]), "r"(a[3]), "r"(b[0]), "r"(b[1]));
}
__device__ __forceinline__ void mma_f16(float* c, const unsigned* a,
                                        const unsigned* b) {
    asm volatile(
        "mma.sync.aligned.m16n8k16.row.col.f32.f16.f16.f32 "
        "{%0,%1,%2,%3}, {%4,%5,%6,%7}, {%8,%9}, {%0,%1,%2,%3};\n"
        : "+f"(c[0]), "+f"(c[1]), "+f"(c[2]), "+f"(c[3])
        : "r"(a[0]), "r"(a[1]), "r"(a[2]), "r"(a[3]), "r"(b[0]), "r"(b[1]));
}
__device__ __forceinline__ void ldsm4(unsigned addr, unsigned& r0, unsigned& r1,
                                      unsigned& r2, unsigned& r3) {
    asm volatile("ldmatrix.sync.aligned.m8n8.x4.shared.b16 {%0,%1,%2,%3}, [%4];"
                 : "=r"(r0), "=r"(r1), "=r"(r2), "=r"(r3) : "r"(addr));
}
__device__ __forceinline__ void ldsm4t(unsigned addr, unsigned& r0, unsigned& r1,
                                       unsigned& r2, unsigned& r3) {
    asm volatile(
        "ldmatrix.sync.aligned.m8n8.x4.trans.shared.b16 {%0,%1,%2,%3}, [%4];"
        : "=r"(r0), "=r"(r1), "=r"(r2), "=r"(r3) : "r"(addr));
}
__device__ __forceinline__ unsigned s2u(const void* p) {
    return (unsigned)__cvta_generic_to_shared(p);
}
__device__ __forceinline__ void cpa16(unsigned dst, const void* src) {
    asm volatile("cp.async.cg.shared.global [%0], [%1], 16;\n" ::"r"(dst),
                 "l"(src));
}
__device__ __forceinline__ void pack_split(float x0, float x1, unsigned& h,
                                           unsigned& l) {
    __nv_bfloat162 hb = __floats2bfloat162_rn(x0, x1);
    float2 hf = __bfloat1622float2(hb);
    __nv_bfloat162 lb = __floats2bfloat162_rn(x0 - hf.x, x1 - hf.y);
    h = *(unsigned*)&hb; l = *(unsigned*)&lb;
}
__device__ __forceinline__ unsigned packh2(float x0, float x1) {
    __half2 t = __floats2half2_rn(x0, x1);
    return *(unsigned*)&t;
}

// ---------------------------------------------------------------------------
// One-shot conversion. fp16 single: x, wqkv, wpos, pos. split-bf16: wout.
// ---------------------------------------------------------------------------
__global__ __launch_bounds__(256) void cvt_all(
    const float* __restrict__ x, const float* __restrict__ wq,
    const float* __restrict__ wp, const float* __restrict__ wo,
    const float* __restrict__ pos) {
    int bid = blockIdx.x;
    if (bid < 10240 || bid >= 10752) {
        const float* src; __half* d; int base;
        if (bid < 8192)       { src = x;   d = g_xf;  base = bid; }
        else if (bid < 9728)  { src = wq;  d = g_wqf; base = bid - 8192; }
        else if (bid < 10240) { src = wp;  d = g_wpf; base = bid - 9728; }
        else                  { src = pos; d = g_psf; base = bid - 10752; }
        int i = base * 256 + threadIdx.x;
        float2 v = ((const float2*)src)[i];
        ((unsigned*)d)[i] = packh2(v.x, v.y);
    } else {
        int i = (bid - 10240) * 256 + threadIdx.x;
        float2 v = ((const float2*)wo)[i];
        unsigned h, l;
        pack_split(v.x, v.y, h, l);
        ((unsigned*)g_woh)[i] = h;
        ((unsigned*)g_wol)[i] = l;
    }
}

// ---------------------------------------------------------------------------
// Split-bf16 GEMM mainloop (K=512, 128x128 tile, cp.async dbuf) — out-proj.
// ---------------------------------------------------------------------------
#define GT 10240
#define GSTAGE (4 * GT)
#define GSM (2 * GSTAGE)

#define GEMM_MAIN(Ah, Al, Wh, Wl, m0, n0, acc)                                  \
    {                                                                           \
        const unsigned sb = s2u(smem);                                          \
        const int lrow = tid >> 2, lc = (tid & 3) << 3;                         \
        auto issue = [&](int k0, int bb) {                                      \
            unsigned base = sb + bb * GSTAGE;                                   \
            _Pragma("unroll") for (int t = 0; t < 2; t++) {                     \
                int row = lrow + t * 64;                                        \
                unsigned so = (unsigned)row * 80 + ((unsigned)lc << 1);         \
                size_t ao = (size_t)(m0 + row) * 512 + k0 + lc;                 \
                size_t wo_ = (size_t)(n0 + row) * 512 + k0 + lc;                \
                cpa16(base + so, Ah + ao);                                      \
                cpa16(base + GT + so, Al + ao);                                 \
                cpa16(base + 2 * GT + so, Wh + wo_);                            \
                cpa16(base + 3 * GT + so, Wl + wo_);                            \
            }                                                                   \
            asm volatile("cp.async.commit_group;\n" ::: "memory");              \
        };                                                                      \
        issue(0, 0);                                                            \
        for (int s = 0; s < 16; s++) {                                          \
            const int bb = s & 1;                                               \
            __syncthreads();                                                    \
            if (s < 15) {                                                       \
                issue((s + 1) << 5, bb ^ 1);                                    \
                asm volatile("cp.async.wait_group 1;\n" ::: "memory");          \
            } else {                                                            \
                asm volatile("cp.async.wait_group 0;\n" ::: "memory");          \
            }                                                                   \
            __syncthreads();                                                    \
            unsigned base = sb + bb * GSTAGE;                                   \
            _Pragma("unroll") for (int kc = 0; kc < 2; kc++) {                  \
                const int kk = kc << 4;                                         \
                unsigned ah[4][4], al[4][4], bh[4][2], bl[4][2];                \
                _Pragma("unroll") for (int mt = 0; mt < 4; mt++) {              \
                    unsigned off = ((aRow + mt * 16) * 40 + kk + aCol) * 2;     \
                    ldsm4(base + off, ah[mt][0], ah[mt][1], ah[mt][2],          \
                          ah[mt][3]);                                           \
                    ldsm4(base + GT + off, al[mt][0], al[mt][1], al[mt][2],     \
                          al[mt][3]);                                           \
                }                                                               \
                _Pragma("unroll") for (int np = 0; np < 2; np++) {              \
                    unsigned off = ((bRow + np * 16) * 40 + kk + bCol) * 2;     \
                    unsigned r0, r1, r2, r3;                                    \
                    ldsm4(base + 2 * GT + off, r0, r1, r2, r3);                 \
                    bh[np * 2][0] = r0; bh[np * 2][1] = r1;                     \
                    bh[np * 2 + 1][0] = r2; bh[np * 2 + 1][1] = r3;             \
                    ldsm4(base + 3 * GT + off, r0, r1, r2, r3);                 \
                    bl[np * 2][0] = r0; bl[np * 2][1] = r1;                     \
                    bl[np * 2 + 1][0] = r2; bl[np * 2 + 1][1] = r3;             \
                }                                                               \
                _Pragma("unroll") for (int mt = 0; mt < 4; mt++)                \
                    _Pragma("unroll") for (int nt = 0; nt < 4; nt++) {          \
                        mma_bf16(acc[mt][nt], ah[mt], bh[nt]);                  \
                        mma_bf16(acc[mt][nt], al[mt], bh[nt]);                  \
                        mma_bf16(acc[mt][nt], ah[mt], bl[nt]);                  \
                    }                                                           \
            }                                                                   \
        }                                                                       \
    }

// ---------------------------------------------------------------------------
// fp16-single GEMM mainloop — qkv/pos.
// ---------------------------------------------------------------------------
#define FT 10240
#define FSTAGE (2 * FT)
#define FSM (2 * FSTAGE)

#define GEMM_MAIN_F16(Af, Wf, m0, n0, acc)                                      \
    {                                                                           \
        const unsigned sb = s2u(smem);                                          \
        const int lrow = tid >> 2, lc = (tid & 3) << 3;                         \
        auto issue = [&](int k0, int bb) {                                      \
            unsigned base = sb + bb * FSTAGE;                                   \
            _Pragma("unroll") for (int t = 0; t < 2; t++) {                     \
                int row = lrow + t * 64;                                        \
                unsigned so = (unsigned)row * 80 + ((unsigned)lc << 1);         \
                cpa16(base + so, Af + (size_t)(m0 + row) * 512 + k0 + lc);      \
                cpa16(base + FT + so, Wf + (size_t)(n0 + row) * 512 + k0 + lc); \
            }                                                                   \
            asm volatile("cp.async.commit_group;\n" ::: "memory");              \
        };                                                                      \
        issue(0, 0);                                                            \
        for (int s = 0; s < 16; s++) {                                          \
            const int bb = s & 1;                                               \
            __syncthreads();                                                    \
            if (s < 15) {                                                       \
                issue((s + 1) << 5, bb ^ 1);                                    \
                asm volatile("cp.async.wait_group 1;\n" ::: "memory");          \
            } else {                                                            \
                asm volatile("cp.async.wait_group 0;\n" ::: "memory");          \
            }                                                                   \
            __syncthreads();                                                    \
            unsigned base = sb + bb * FSTAGE;                                   \
            _Pragma("unroll") for (int kc = 0; kc < 2; kc++) {                  \
                const int kk = kc << 4;                                         \
                unsigned af[4][4], bf[4][2];                                    \
                _Pragma("unroll") for (int mt = 0; mt < 4; mt++) {              \
                    unsigned off = ((aRow + mt * 16) * 40 + kk + aCol) * 2;     \
                    ldsm4(base + off, af[mt][0], af[mt][1], af[mt][2],          \
                          af[mt][3]);                                           \
                }                                                               \
                _Pragma("unroll") for (int np = 0; np < 2; np++) {              \
                    unsigned off = ((bRow + np * 16) * 40 + kk + bCol) * 2;     \
                    unsigned r0, r1, r2, r3;                                    \
                    ldsm4(base + FT + off, r0, r1, r2, r3);                     \
                    bf[np * 2][0] = r0; bf[np * 2][1] = r1;                     \
                    bf[np * 2 + 1][0] = r2; bf[np * 2 + 1][1] = r3;             \
                }                                                               \
                _Pragma("unroll") for (int mt = 0; mt < 4; mt++)                \
                    _Pragma("unroll") for (int nt = 0; nt < 4; nt++)            \
                        mma_f16(acc[mt][nt], af[mt], bf[nt]);                   \
            }                                                                   \
        }                                                                       \
    }

// ---------------------------------------------------------------------------
// Fused qkv-proj + pos-proj GEMM (fp16 single). 1-D grid, 832 blocks.
// ---------------------------------------------------------------------------
__global__ __launch_bounds__(256, 2) void gemm_qkv_pos() {
    extern __shared__ char smem[];
    const int tid = threadIdx.x, l = tid & 31, w = tid >> 5;
    const int wm = w >> 2, wn = w & 3;
    const int aRow = wm * 64 + (l & 15);
    const int aCol = (l & 16) >> 1;
    const int bRow = wn * 32 + (l & 7) + ((l & 16) >> 1);
    const int bCol = l & 8;

    const int bid = blockIdx.x;
    const __half *Af, *Wf;
    int m0, n0, mode;
    if (bid < 768) {
        Af = g_xf; Wf = g_wqf;
        m0 = (bid / 12) << 7; n0 = (bid % 12) << 7; mode = 1;
    } else {
        int t = bid - 768;
        Af = g_psf; Wf = g_wpf;
        m0 = (t >> 2) << 7; n0 = (t & 3) << 7; mode = 2;
    }

    float acc[4][4][4];
#pragma unroll
    for (int i = 0; i < 4; i++)
#pragma unroll
        for (int j = 0; j < 4; j++)
#pragma unroll
            for (int e = 0; e < 4; e++) acc[i][j][e] = 0.f;

    GEMM_MAIN_F16(Af, Wf, m0, n0, acc);

    const int er = m0 + wm * 64 + (l >> 2);
    const int ec = n0 + wn * 32 + ((l & 3) << 1);
#pragma unroll
    for (int mt = 0; mt < 4; mt++) {
#pragma unroll
        for (int nt = 0; nt < 4; nt++) {
            int col = ec + nt * 8;
#pragma unroll
            for (int half = 0; half < 2; half++) {
                int r = er + mt * 16 + half * 8;
                float a0 = acc[mt][nt][half * 2];
                float a1 = acc[mt][nt][half * 2 + 1];
                if (mode == 1) {
                    int hh_ = col / 192;
                    int rem = col - hh_ * 192;
                    int part = rem >> 6, d = rem & 63;
                    if (part == 0) {
                        *(float2*)&g_q[(size_t)r * 512 + hh_ * 64 + d] =
                            make_float2(a0, a1);
                    } else {
                        int b = r >> 10, ll2 = r & 1023;
                        size_t idx =
                            (((size_t)(b * 8 + hh_)) * 1024 + ll2) * 64 + d;
                        __half2 hv = __floats2half2_rn(a0, a1);
                        if (part == 1) *(__half2*)&g_k[idx] = hv;
                        else           *(__half2*)&g_v[idx] = hv;
                    }
                } else {
                    int hh_ = col >> 6, d = col & 63;
                    size_t idx = (((size_t)hh_) * 2048 + r) * 64 + d;
                    *(__half2*)&g_p[idx] = __floats2half2_rn(a0, a1);
                }
            }
        }
    }
}

// ---------------------------------------------------------------------------
// Standalone out-proj GEMM (split bf16): out = ctx @ wout^T + bias.
// ---------------------------------------------------------------------------
__global__ __launch_bounds__(256, 2) void gemm_out(
    const float* __restrict__ bias, float* __restrict__ C_ext) {
    extern __shared__ char smem[];
    const int tid = threadIdx.x, l = tid & 31, w = tid >> 5;
    const int wm = w >> 2, wn = w & 3;
    const int aRow = wm * 64 + (l & 15);
    const int aCol = (l & 16) >> 1;
    const int bRow = wn * 32 + (l & 7) + ((l & 16) >> 1);
    const int bCol = l & 8;
    const int m0 = blockIdx.y << 7, n0 = blockIdx.x << 7;

    float acc[4][4][4];
#pragma unroll
    for (int i = 0; i < 4; i++)
#pragma unroll
        for (int j = 0; j < 4; j++)
#pragma unroll
            for (int e = 0; e < 4; e++) acc[i][j][e] = 0.f;

    GEMM_MAIN(g_cth, g_ctl, g_woh, g_wol, m0, n0, acc);

    const int er = m0 + wm * 64 + (l >> 2);
    const int ec = n0 + wn * 32 + ((l & 3) << 1);
#pragma unroll
    for (int mt = 0; mt < 4; mt++) {
#pragma unroll
        for (int nt = 0; nt < 4; nt++) {
            int col = ec + nt * 8;
            float2 bb2 = *(const float2*)&bias[col];
#pragma unroll
            for (int half = 0; half < 2; half++) {
                int r = er + mt * 16 + half * 8;
                *(float2*)&C_ext[(size_t)r * 512 + col] =
                    make_float2(acc[mt][nt][half * 2] + bb2.x,
                                acc[mt][nt][half * 2 + 1] + bb2.y);
            }
        }
    }
}

// ---------------------------------------------------------------------------
// Fused attention. Grid (8, 64), 256 thr, 2 CTA/SM.
// Mainloop stores exp'd probs fp16 to g_attn_raw (same fp16 values the ctx
// MMA consumes). Tail: multiply-only normalize from warm-L2 fp16 block,
// write fp32 to output.
// ---------------------------------------------------------------------------
#define AP0 0
#define AK0 55296
#define AV0 73728
#define ASCRH 92160
#define AINV ASCRH
#define SM_BYTES_A 113664

__global__ __launch_bounds__(256, 2) void attn_kernel(
    const float* __restrict__ ubias, const float* __restrict__ vbias,
    float* __restrict__ attn, int do_out) {
    extern __shared__ char smem[];

    const int tid = threadIdx.x, l = tid & 31, w = tid >> 5;
    const int bh = blockIdx.y, b = bh >> 3, h = bh & 7;
    const int q0 = blockIdx.x << 7;
    const int qs = w << 4;
    const float scale = 0.04419417382415922f;  // 1/sqrt(512)

    const unsigned pB0 = s2u(smem + AP0);
    const unsigned kB0 = s2u(smem + AK0);
    const unsigned vB0 = s2u(smem + AV0);
    __half* scrh = (__half*)(smem + ASCRH) + w * 16 * 84;

    // ---- QU/QV staging (overlaps P buffers; consumed before first tile) ----
    {
        __half* QU = (__half*)(smem + 0);
        __half* QV = (__half*)(smem + 18432);
        for (int idx = tid; idx < 4096; idx += 256) {
            int qi = idx >> 5, d2 = (idx & 31) << 1;
            float2 qv = *(const float2*)&g_q[((size_t)(b * Lc + q0 + qi)) * 512 +
                                             h * 64 + d2];
            *(unsigned*)&QU[qi * 72 + d2] =
                packh2((qv.x + ubias[h * 64 + d2]) * scale,
                       (qv.y + ubias[h * 64 + d2 + 1]) * scale);
            *(unsigned*)&QV[qi * 72 + d2] =
                packh2((qv.x + vbias[h * 64 + d2]) * scale,
                       (qv.y + vbias[h * 64 + d2 + 1]) * scale);
        }
    }
    __syncthreads();

    unsigned au[4][4], av[4][4];
    {
        unsigned baseU = s2u(smem + 0), baseV = s2u(smem + 18432);
        int row = qs + (l & 15), colp = (l & 16) >> 1;
#pragma unroll
        for (int kc = 0; kc < 4; kc++) {
            unsigned off = (row * 72 + kc * 16 + colp) * 2;
            ldsm4(baseU + off, au[kc][0], au[kc][1], au[kc][2], au[kc][3]);
            ldsm4(baseV + off, av[kc][0], av[kc][1], av[kc][2], av[kc][3]);
        }
    }
    __syncthreads();

    auto issue_tile = [&](int kt0, int bb) {
        size_t gb = (((size_t)bh) * 1024 + kt0) * 64;
        const uint4* GK = (const uint4*)(g_k + gb);
        const uint4* GV = (const uint4*)(g_v + gb);
        int pbase = kt0 - q0 + 896;
        const uint4* GP = (const uint4*)(g_p + (((size_t)h) * 2048 + pbase) * 64);
        unsigned kb = kB0 + bb * 9216;
        unsigned vb = vB0 + bb * 9216;
        unsigned pb = pB0 + bb * 27648;
#pragma unroll
        for (int t = 0; t < 2; t++) {
            int i = tid + t * 256;
            unsigned so = (unsigned)((i >> 3) * 9 + (i & 7)) * 16;
            cpa16(kb + so, GK + i);
            cpa16(vb + so, GV + i);
        }
#pragma unroll
        for (int t = 0; t < 6; t++) {
            int i = tid + t * 256;
            unsigned so = (unsigned)((i >> 3) * 9 + (i & 7)) * 16;
            cpa16(pb + so, GP + i);
        }
        asm volatile("cp.async.commit_group;\n" ::: "memory");
    };

    issue_tile(0, 0);

    float ct[8][4];
#pragma unroll
    for (int nt = 0; nt < 8; nt++)
#pragma unroll
        for (int e = 0; e < 4; e++) ct[nt][e] = 0.f;
    float rs_lo = 0.f, rs_hi = 0.f;

    const int nlane = (l & 7) + ((l & 16) >> 1);
    const int klane = l & 8;
    const int tkl = (l & 7) + (l & 8);
    const int tnl = (l & 16) >> 1;
    const int r0w = 112 - qs;

    for (int kt = 0; kt < 16; kt++) {
        const int bb = kt & 1;
        const int kt0 = kt << 6;
        __syncthreads();
        if (kt < 15) {
            issue_tile(kt0 + 64, bb ^ 1);
            asm volatile("cp.async.wait_group 1;\n" ::: "memory");
        } else {
            asm volatile("cp.async.wait_group 0;\n" ::: "memory");
        }
        __syncthreads();

        const unsigned kB = kB0 + bb * 9216;
        const unsigned vB = vB0 + bb * 9216;
        const unsigned pB = pB0 + bb * 27648;

        float bd[10][4];
#pragma unroll
        for (int nt = 0; nt < 10; nt++)
#pragma unroll
            for (int e = 0; e < 4; e++) bd[nt][e] = 0.f;
#pragma unroll
        for (int np = 0; np < 5; np++) {
            int nb = r0w + np * 16 + nlane;
#pragma unroll
            for (int kc = 0; kc < 4; kc++) {
                unsigned r0, r1, r2, r3;
                ldsm4(pB + (nb * 72 + kc * 16 + klane) * 2, r0, r1, r2, r3);
                unsigned b0[2] = {r0, r1}, b1[2] = {r2, r3};
                mma_f16(bd[np * 2], av[kc], b0);
                mma_f16(bd[np * 2 + 1], av[kc], b1);
            }
        }
        {
            int r = l >> 2, col = ((l & 3) << 1);
#pragma unroll
            for (int nt = 0; nt < 10; nt++) {
                *(__half2*)&scrh[r * 84 + nt * 8 + col] =
                    __floats2half2_rn(bd[nt][0], bd[nt][1]);
                *(__half2*)&scrh[(r + 8) * 84 + nt * 8 + col] =
                    __floats2half2_rn(bd[nt][2], bd[nt][3]);
            }
        }
        __syncwarp();

        float sc[8][4];
#pragma unroll
        for (int nt = 0; nt < 8; nt++)
#pragma unroll
            for (int e = 0; e < 4; e++) sc[nt][e] = 0.f;
#pragma unroll
        for (int np = 0; np < 4; np++) {
            int nb = np * 16 + nlane;
#pragma unroll
            for (int kc = 0; kc < 4; kc++) {
                unsigned r0, r1, r2, r3;
                ldsm4(kB + (nb * 72 + kc * 16 + klane) * 2, r0, r1, r2, r3);
                unsigned b0[2] = {r0, r1}, b1[2] = {r2, r3};
                mma_f16(sc[np * 2], au[kc], b0);
                mma_f16(sc[np * 2 + 1], au[kc], b1);
            }
        }

        // ---- add banded bd; exp; rowsum; pack fp16 probs; store + ctx ----
        {
            int r = l >> 2;
#pragma unroll
            for (int nt = 0; nt < 8; nt++) {
                int kk = nt * 8 + ((l & 3) << 1);
                int j = kk - r + 15;
                sc[nt][0] += __half2float(scrh[r * 84 + j]);
                sc[nt][1] += __half2float(scrh[r * 84 + j + 1]);
                int j2 = kk - (r + 8) + 15;
                sc[nt][2] += __half2float(scrh[(r + 8) * 84 + j2]);
                sc[nt][3] += __half2float(scrh[(r + 8) * 84 + j2 + 1]);
            }
#pragma unroll
            for (int nt = 0; nt < 8; nt++) {
#pragma unroll
                for (int e = 0; e < 4; e++) sc[nt][e] = __expf(sc[nt][e]);
                rs_lo += sc[nt][0] + sc[nt][1];
                rs_hi += sc[nt][2] + sc[nt][3];
            }
            size_t rbase =
                ((size_t)bh * Lc + (q0 + qs + r)) * Lc + kt0 + ((l & 3) << 1);
#pragma unroll
            for (int nt = 0; nt < 8; nt++) {
                *(__half2*)&g_attn_raw[rbase + nt * 8] =
                    __floats2half2_rn(sc[nt][0], sc[nt][1]);
                *(__half2*)&g_attn_raw[rbase + 8 * Lc + nt * 8] =
                    __floats2half2_rn(sc[nt][2], sc[nt][3]);
            }
        }

        // ---- ctx += P @ V (uses the same fp16 quantization as the store) ----
#pragma unroll
        for (int kc = 0; kc < 4; kc++) {
            unsigned pa[4];
            pa[0] = packh2(sc[2 * kc][0], sc[2 * kc][1]);
            pa[1] = packh2(sc[2 * kc][2], sc[2 * kc][3]);
            pa[2] = packh2(sc[2 * kc + 1][0], sc[2 * kc + 1][1]);
            pa[3] = packh2(sc[2 * kc + 1][2], sc[2 * kc + 1][3]);
            int krow = kc * 16 + tkl;
#pragma unroll
            for (int np = 0; np < 4; np++) {
                unsigned r0, r1, r2, r3;
                ldsm4t(vB + (krow * 72 + np * 16 + tnl) * 2, r0, r1, r2, r3);
                unsigned b0[2] = {r0, r1}, b1[2] = {r2, r3};
                mma_f16(ct[np * 2], pa, b0);
                mma_f16(ct[np * 2 + 1], pa, b1);
            }
        }
    }

    // ---- rowsum reduce; INV to smem (scr dead); ctx planes ----
    rs_lo += __shfl_xor_sync(0xffffffffu, rs_lo, 1);
    rs_lo += __shfl_xor_sync(0xffffffffu, rs_lo, 2);
    rs_hi += __shfl_xor_sync(0xffffffffu, rs_hi, 1);
    rs_hi += __shfl_xor_sync(0xffffffffu, rs_hi, 2);
    float inv_lo = 1.f / rs_lo, inv_hi = 1.f / rs_hi;
    __syncthreads();                 // all warps done with scr before INV write
    float* INV = (float*)(smem + AINV);
    int r = l >> 2;
    if ((l & 3) == 0) {
        INV[qs + r] = inv_lo;
        INV[qs + r + 8] = inv_hi;
    }
    size_t cbase = ((size_t)(b * Lc + q0 + qs + r)) * 512 + h * 64 + ((l & 3) << 1);
#pragma unroll
    for (int nt = 0; nt < 8; nt++) {
        unsigned hh, lo;
        pack_split(ct[nt][0] * inv_lo, ct[nt][1] * inv_lo, hh, lo);
        *(unsigned*)&g_cth[cbase + nt * 8] = hh;
        *(unsigned*)&g_ctl[cbase + nt * 8] = lo;
        pack_split(ct[nt][2] * inv_hi, ct[nt][3] * inv_hi, hh, lo);
        *(unsigned*)&g_cth[cbase + 8 * 512 + nt * 8] = hh;
        *(unsigned*)&g_ctl[cbase + 8 * 512 + nt * 8] = lo;
    }

    // ---- tail normalize: fp16 probs (warm L2) * inv -> fp32 output ----
    __syncthreads();
    if (do_out) {
        const uint4* R4 =
            (const uint4*)(g_attn_raw + ((size_t)bh * Lc + q0) * Lc);
        float4* O = (float4*)(attn + ((size_t)bh * Lc + q0) * Lc);
#pragma unroll
        for (int it = 0; it < 16; it++) {
            int id[4]; uint4 rv[4]; float iv[4];
#pragma unroll
            for (int j = 0; j < 4; j++) {
                id[j] = tid + (it * 4 + j) * 256;
                rv[j] = R4[id[j]];
            }
#pragma unroll
            for (int j = 0; j < 4; j++) iv[j] = INV[id[j] >> 7];
#pragma unroll
            for (int j = 0; j < 4; j++) {
                const __half2* hp = (const __half2*)&rv[j];
                float2 p0 = __half22float2(hp[0]);
                float2 p1 = __half22float2(hp[1]);
                float2 p2 = __half22float2(hp[2]);
                float2 p3 = __half22float2(hp[3]);
                O[2 * id[j]] = make_float4(p0.x * iv[j], p0.y * iv[j],
                                           p1.x * iv[j], p1.y * iv[j]);
                O[2 * id[j] + 1] = make_float4(p2.x * iv[j], p2.y * iv[j],
                                               p3.x * iv[j], p3.y * iv[j]);
            }
        }
    }
}

// ---------------------------------------------------------------------------
extern "C" void kernel_launch(void* const* d_in, const int* in_sizes, int n_in,
                              void* d_out, int out_size) {
    const float* x    = (const float*)d_in[0];
    const float* pos  = (const float*)d_in[1];
    const float* wqkv = (const float*)d_in[2];
    const float* wpos = (const float*)d_in[3];
    const float* wout = (const float*)d_in[4];
    const float* bout = (const float*)d_in[5];
    const float* ub   = (const float*)d_in[6];
    const float* vb   = (const float*)d_in[7];
    float* out = (float*)d_out;

    int attn_in_out = ((long long)out_size >= (long long)OUT_ELEMS + ATTN_ELEMS);
    float* attn_buf = out + OUT_ELEMS;

    cvt_all<<<12799, 256>>>(x, wqkv, wpos, wout, pos);

    cudaFuncSetAttribute(gemm_qkv_pos, cudaFuncAttributeMaxDynamicSharedMemorySize,
                         FSM);
    gemm_qkv_pos<<<832, 256, FSM>>>();

    cudaFuncSetAttribute(attn_kernel, cudaFuncAttributeMaxDynamicSharedMemorySize,
                         SM_BYTES_A);
    attn_kernel<<<dim3(8, 64), 256, SM_BYTES_A>>>(ub, vb, attn_buf,
                                                  attn_in_out ? 1 : 0);

    cudaFuncSetAttribute(gemm_out, cudaFuncAttributeMaxDynamicSharedMemorySize,
                         GSM);
    gemm_out<<<dim3(4, 64), 256, GSM>>>(bout, out);
}